// round 7
// baseline (speedup 1.0000x reference)
#include <cuda_runtime.h>
#include <cstdint>

// Problem constants
#define BB 64
#define SS 512
#define HH 768
#define EE 128
#define TT_ 4
#define NT 5
#define H4 192   // H/4 float4 lanes

// Scratch (no allocs allowed)
__device__ float g_rowcoef[BB * SS * 8];   // {at0..at4, ac, 0, 0} per (b,s)

// ---------------------------------------------------------------------------
// P: per-batch coefficient build. One block per batch b (512 threads, one per
// flat (e,t)). Histogram into smem via atomics, then write 512 rows x 8 floats.
// ---------------------------------------------------------------------------
__global__ void __launch_bounds__(512) rowcoef_kernel(
    const int* __restrict__ ent_tokens,     // [E,T]
    const int* __restrict__ types,          // [B,E]
    const float* __restrict__ conf) {       // [B,E]
    __shared__ float sm[SS * 6];
    int b = blockIdx.x;
    int tid = threadIdx.x;                  // 0..511 == flat (e,t)

#pragma unroll
    for (int j = 0; j < 6; j++) sm[tid + j * SS] = 0.f;
    __syncthreads();

    int tok = ent_tokens[tid];
    int e = tid >> 2;
    int ty = types[b * EE + e];
    float c = conf[b * EE + e];
    atomicAdd(&sm[tok * 6 + ty], 1.f);
    atomicAdd(&sm[tok * 6 + 5], c);
    __syncthreads();

    float4* o = reinterpret_cast<float4*>(&g_rowcoef[((size_t)b * SS + tid) * 8]);
    o[0] = make_float4(sm[tid * 6 + 0], sm[tid * 6 + 1], sm[tid * 6 + 2], sm[tid * 6 + 3]);
    o[1] = make_float4(sm[tid * 6 + 4], sm[tid * 6 + 5], 0.f, 0.f);
}

// ---------------------------------------------------------------------------
// Fused main kernel: persistent grid-stride + smem tables + uniform-sparsity
// combine + SOFTWARE PIPELINE (prefetch next task's coef+hidden one iteration
// ahead so each warp always has an outstanding 512B streaming read).
// Emb tasks computed directly from hidden + coefficients (L2-hot gather).
// ---------------------------------------------------------------------------
__global__ void __launch_bounds__(H4, 8) fused_kernel(
    const float* __restrict__ hidden,       // [B,S,H]
    const int* __restrict__ ent_tokens,     // [E,T]
    const float* __restrict__ type_table,   // [NT,H]
    const float* __restrict__ conf_w,       // [H]
    const float* __restrict__ conf_b,       // [H]
    float* __restrict__ out_enh,            // [B,S,H]
    float* __restrict__ out_emb) {          // [B,E,H]
    __shared__ float4 s_tab[NT + 1][H4];    // [0..4]=type_table+conf_b, [5]=conf_w
    int tid = threadIdx.x;                  // 0..191
    int h = tid * 4;

    {
        float4 cb4 = *reinterpret_cast<const float4*>(conf_b + h);
        s_tab[NT][tid] = *reinterpret_cast<const float4*>(conf_w + h);
#pragma unroll
        for (int ty = 0; ty < NT; ty++) {
            float4 v = *reinterpret_cast<const float4*>(type_table + ty * HH + h);
            s_tab[ty][tid] = make_float4(v.x + cb4.x, v.y + cb4.y, v.z + cb4.z, v.w + cb4.w);
        }
    }
    __syncthreads();

    const int NTASK = BB * (SS + EE);
    const int stride = gridDim.x;

    // pipeline stage loader: for enhance tasks, issue coef + hidden LDGs
    auto stage_load = [&](int i, int& sb, int& sr, float4& sh, float4& s0, float4& s1) {
        sb = i / (SS + EE);
        sr = i - sb * (SS + EE);
        if (sr < SS) {
            const float4* cf = reinterpret_cast<const float4*>(
                &g_rowcoef[((size_t)sb * SS + sr) * 8]);
            s0 = __ldg(cf);
            s1 = __ldg(cf + 1);
            sh = *reinterpret_cast<const float4*>(
                hidden + ((size_t)sb * SS + sr) * HH + h);
        }
    };

    int idx = blockIdx.x;
    int cb_, cr_;
    float4 chid, cc0, cc1;
    if (idx < NTASK) stage_load(idx, cb_, cr_, chid, cc0, cc1);

    while (idx < NTASK) {
        int nidx = idx + stride;
        int nb, nr;
        float4 nh, n0, n1;
        if (nidx < NTASK) stage_load(nidx, nb, nr, nh, n0, n1);

        // ---- consume current task ----
        if (cr_ < SS) {
            // enhance row (cb_, cr_): data already in flight from stage_load
            float4 v = chid;
            float a[NT + 1] = {cc0.x, cc0.y, cc0.z, cc0.w, cc1.x, cc1.y};
            bool any = (cc0.x != 0.f) | (cc0.y != 0.f) | (cc0.z != 0.f) |
                       (cc0.w != 0.f) | (cc1.x != 0.f) | (cc1.y != 0.f);
            if (any) {
#pragma unroll
                for (int j = 0; j < NT + 1; j++) {
                    if (a[j] != 0.f) {      // uniform across block
                        float4 t = s_tab[j][tid];
                        v.x += a[j] * t.x; v.y += a[j] * t.y;
                        v.z += a[j] * t.z; v.w += a[j] * t.w;
                    }
                }
            }
            *reinterpret_cast<float4*>(
                out_enh + ((size_t)cb_ * SS + cr_) * HH + h) = v;
        } else {
            // entity embedding (cb_, e): 0.25 * sum_t enhanced[b, tok, :]
            int e = cr_ - SS;
            const float* hb = hidden + (size_t)cb_ * SS * HH;
            float4 acc = make_float4(0.f, 0.f, 0.f, 0.f);
            float a0 = 0.f, a1 = 0.f, a2 = 0.f, a3 = 0.f, a4 = 0.f, ac = 0.f;
#pragma unroll
            for (int t = 0; t < TT_; t++) {
                int s = __ldg(&ent_tokens[e * TT_ + t]);
                const float4* cf = reinterpret_cast<const float4*>(
                    &g_rowcoef[((size_t)cb_ * SS + s) * 8]);
                float4 c0 = __ldg(cf);
                float4 c1 = __ldg(cf + 1);
                a0 += c0.x; a1 += c0.y; a2 += c0.z; a3 += c0.w; a4 += c1.x; ac += c1.y;
                float4 v = *reinterpret_cast<const float4*>(hb + (size_t)s * HH + h);
                acc.x += v.x; acc.y += v.y; acc.z += v.z; acc.w += v.w;
            }
            float4 t;
            t = s_tab[0][tid]; acc.x += a0 * t.x; acc.y += a0 * t.y; acc.z += a0 * t.z; acc.w += a0 * t.w;
            t = s_tab[1][tid]; acc.x += a1 * t.x; acc.y += a1 * t.y; acc.z += a1 * t.z; acc.w += a1 * t.w;
            t = s_tab[2][tid]; acc.x += a2 * t.x; acc.y += a2 * t.y; acc.z += a2 * t.z; acc.w += a2 * t.w;
            t = s_tab[3][tid]; acc.x += a3 * t.x; acc.y += a3 * t.y; acc.z += a3 * t.z; acc.w += a3 * t.w;
            t = s_tab[4][tid]; acc.x += a4 * t.x; acc.y += a4 * t.y; acc.z += a4 * t.z; acc.w += a4 * t.w;
            t = s_tab[5][tid]; acc.x += ac * t.x; acc.y += ac * t.y; acc.z += ac * t.z; acc.w += ac * t.w;
            acc.x *= 0.25f; acc.y *= 0.25f; acc.z *= 0.25f; acc.w *= 0.25f;
            *reinterpret_cast<float4*>(
                out_emb + ((size_t)cb_ * EE + e) * HH + h) = acc;
        }

        // rotate pipeline
        idx = nidx;
        cb_ = nb; cr_ = nr;
        chid = nh; cc0 = n0; cc1 = n1;
    }
}

// ---------------------------------------------------------------------------
// Inputs in metadata order:
// 0 hidden_states (B,S,H) f32 | 1 entity_types (B,E) i32 | 2 entity_confidences (B,E) f32
// 3 ent_tokens (E,T) i32 | 4 type_table (NT,H) f32 | 5 conf_w (1,H) f32 | 6 conf_b (H) f32
// Output: enhanced (B,S,H) then entity_embeddings (B,E,H), concatenated.
// ---------------------------------------------------------------------------
extern "C" void kernel_launch(void* const* d_in, const int* in_sizes, int n_in,
                              void* d_out, int out_size) {
    const float* hidden   = (const float*)d_in[0];
    const int*   types    = (const int*)d_in[1];
    const float* conf     = (const float*)d_in[2];
    const int*   ent_tok  = (const int*)d_in[3];
    const float* ttab     = (const float*)d_in[4];
    const float* conf_w   = (const float*)d_in[5];
    const float* conf_b   = (const float*)d_in[6];

    float* out_enh = (float*)d_out;
    float* out_emb = out_enh + (size_t)BB * SS * HH;

    rowcoef_kernel<<<BB, 512>>>(ent_tok, types, conf);
    fused_kernel<<<1184, H4>>>(hidden, ent_tok, ttab, conf_w, conf_b,
                               out_enh, out_emb);
}